// round 5
// baseline (speedup 1.0000x reference)
#include <cuda_runtime.h>
#include <cuda_bf16.h>
#include <math.h>

// Problem constants
#define B   256
#define S   512
#define D   768
#define D4  (D/4)        // 192 float4 per row
#define K4D 3072         // 4*D
#define H1  256
#define H2  64
#define L   4

// GEMM1 tiling
#define BM  32
#define BN  64
#define BK  32
#define KS  8
#define KC  (K4D/KS)     // 384 k per split
#define FS  68           // padded fsh2 row stride (floats): 16B-aligned, conflict-reduced

// Scratch (device globals — no allocation allowed)
__device__ float g_f[B * K4D];            // features [256, 3072]  (3 MB)
__device__ float g_h1p[KS * B * H1];      // GEMM1 partials [8, 256, 256] (2 MB)

#define FFMA2(d, a, b) \
    asm("fma.rn.f32x2 %0, %1, %2, %0;" : "+l"(d) : "l"(a), "l"(b))

// ---------------------------------------------------------------------------
// K1: feature extraction. grid (B, 2, 3): sample, x1/x2, 64-float4 col chunk.
// 256 threads: col = t%64, rowgroup = t/64 (4-way), span loop unrolled x2.
// ---------------------------------------------------------------------------
__global__ void __launch_bounds__(256) feat_kernel(
    const float* __restrict__ x1, const float* __restrict__ x2,
    const int* __restrict__ s1a, const int* __restrict__ e1a,
    const int* __restrict__ s2a, const int* __restrict__ e2a)
{
    __shared__ float4 part[4][64];        // 4 KB

    const int b   = blockIdx.x;
    const int sel = blockIdx.y;
    const int ch  = blockIdx.z;           // column chunk 0..2
    const int t   = threadIdx.x;
    const int col = t & 63;
    const int rg  = t >> 6;

    const float* x = sel ? x2 : x1;
    int s = sel ? s2a[b] : s1a[b];
    int e = sel ? e2a[b] : e1a[b];
    e = max(e, s + 1);
    int lo = max(s, 0), hi = min(e, S);
    int cnt = max(hi - lo, 1);
    float inv = 1.0f / (float)cnt;

    const float4* x4 = reinterpret_cast<const float4*>(x);
    float4* f4 = reinterpret_cast<float4*>(g_f);
    const long base = (long)b * S * D4 + ch * 64;
    const long frow = (long)b * (K4D / 4) + sel * (2 * D4) + ch * 64;

    // CLS copy (rowgroup 0: 64 threads cover this 64-float4 chunk)
    if (rg == 0)
        f4[frow + col] = x4[base + col];

    // strided partial sums, 2 loads in flight
    float4 acc = make_float4(0.f, 0.f, 0.f, 0.f);
    int r = lo + rg;
    for (; r + 4 < hi; r += 8) {
        float4 v0 = x4[base + (long)r * D4 + col];
        float4 v1 = x4[base + (long)(r + 4) * D4 + col];
        acc.x += v0.x + v1.x; acc.y += v0.y + v1.y;
        acc.z += v0.z + v1.z; acc.w += v0.w + v1.w;
    }
    if (r < hi) {
        float4 v = x4[base + (long)r * D4 + col];
        acc.x += v.x; acc.y += v.y; acc.z += v.z; acc.w += v.w;
    }
    part[rg][col] = acc;
    __syncthreads();

    if (t < 64) {
        float4 a0 = part[0][t], a1 = part[1][t], a2 = part[2][t], a3 = part[3][t];
        float4 o;
        o.x = (a0.x + a1.x + a2.x + a3.x) * inv;
        o.y = (a0.y + a1.y + a2.y + a3.y) * inv;
        o.z = (a0.z + a1.z + a2.z + a3.z) * inv;
        o.w = (a0.w + a1.w + a2.w + a3.w) * inv;
        f4[frow + D4 + t] = o;
    }
}

// ---------------------------------------------------------------------------
// K2: GEMM1 split-K, 32x64 tile, 4x4 micro-tile, packed f32x2 FMA.
// f tile stored DUPLICATED in smem ({v,v} float2) so the broadcast operand of
// fma.rn.f32x2 loads directly as a register pair — no pack MOVs.
// grid (B/BM=8, H1/BN=4, KS=8) = 256 blocks, 128 threads.
// ---------------------------------------------------------------------------
__global__ void __launch_bounds__(128) gemm1_kernel(
    const float* __restrict__ W1, const float* __restrict__ b1)
{
    __shared__ float fsh2[BK][FS];        // duplicated f tile, padded: 8.5 KB
    __shared__ float wsh[BK][BN];         // 8 KB

    const int m0 = blockIdx.x * BM;
    const int n0 = blockIdx.y * BN;
    const int kz = blockIdx.z;
    const int k0 = kz * KC;

    const int tid = threadIdx.x;
    const int tx = tid % 16;              // col group: 4 cols each -> 64
    const int ty = tid / 16;              // row group: 4 rows each -> 32

    const float4* gf4 = reinterpret_cast<const float4*>(g_f);
    const float4* w4  = reinterpret_cast<const float4*>(W1);

    const int kq   = tid % 8;
    const int mrow = tid / 8;
    const int nq  = tid % 16;
    const int kr0 = tid / 16;

    unsigned long long acc2[4][2];
    #pragma unroll
    for (int r = 0; r < 4; ++r) { acc2[r][0] = 0ull; acc2[r][1] = 0ull; }

    for (int kt = 0; kt < KC; kt += BK) {
        // load f tile: BM x BK, duplicated per element
        #pragma unroll
        for (int i = 0; i < 2; ++i) {
            int m = mrow + i * 16;
            float4 v = gf4[(long)(m0 + m) * (K4D / 4) + (k0 + kt) / 4 + kq];
            *reinterpret_cast<float2*>(&fsh2[kq * 4 + 0][2 * m]) = make_float2(v.x, v.x);
            *reinterpret_cast<float2*>(&fsh2[kq * 4 + 1][2 * m]) = make_float2(v.y, v.y);
            *reinterpret_cast<float2*>(&fsh2[kq * 4 + 2][2 * m]) = make_float2(v.z, v.z);
            *reinterpret_cast<float2*>(&fsh2[kq * 4 + 3][2 * m]) = make_float2(v.w, v.w);
        }
        // load w tile: BK x BN
        #pragma unroll
        for (int i = 0; i < 4; ++i) {
            int kr = kr0 + i * 8;
            *reinterpret_cast<float4*>(&wsh[kr][nq * 4]) =
                w4[(long)(k0 + kt + kr) * (H1 / 4) + n0 / 4 + nq];
        }
        __syncthreads();

        #pragma unroll
        for (int k = 0; k < BK; ++k) {
            const ulonglong2* fp =
                reinterpret_cast<const ulonglong2*>(&fsh2[k][2 * (ty * 4)]);
            ulonglong2 fa = fp[0];        // m pairs (ty*4+0), (ty*4+1)
            ulonglong2 fb = fp[1];        // m pairs (ty*4+2), (ty*4+3)
            ulonglong2 wp = *reinterpret_cast<const ulonglong2*>(&wsh[k][tx * 4]);
            FFMA2(acc2[0][0], fa.x, wp.x);  FFMA2(acc2[0][1], fa.x, wp.y);
            FFMA2(acc2[1][0], fa.y, wp.x);  FFMA2(acc2[1][1], fa.y, wp.y);
            FFMA2(acc2[2][0], fb.x, wp.x);  FFMA2(acc2[2][1], fb.x, wp.y);
            FFMA2(acc2[3][0], fb.y, wp.x);  FFMA2(acc2[3][1], fb.y, wp.y);
        }
        __syncthreads();
    }

    // epilogue: unpack, fold bias into split 0, store partials
    float* outp = g_h1p + (long)kz * (B * H1);
    #pragma unroll
    for (int r = 0; r < 4; ++r) {
        int m = m0 + ty * 4 + r;
        #pragma unroll
        for (int p = 0; p < 2; ++p) {
            int n = n0 + tx * 4 + p * 2;
            float lo = __uint_as_float((unsigned)(acc2[r][p] & 0xffffffffull));
            float hi = __uint_as_float((unsigned)(acc2[r][p] >> 32));
            if (kz == 0) { lo += b1[n]; hi += b1[n + 1]; }
            outp[(long)m * H1 + n]     = lo;
            outp[(long)m * H1 + n + 1] = hi;
        }
    }
}

// ---------------------------------------------------------------------------
// K3: per-batch fused tail: reduce split-K partials + ReLU -> GEMM2 + ReLU ->
// GEMM3 -> softmax. One block per batch sample, 256 threads.
// ---------------------------------------------------------------------------
__global__ void __launch_bounds__(H1) tail_kernel(
    const float* __restrict__ W2, const float* __restrict__ b2,
    const float* __restrict__ W3, const float* __restrict__ b3,
    float* __restrict__ out)
{
    __shared__ float hsh[H1];
    __shared__ float p2sh[4][H2];
    __shared__ float h2sh[H2];
    __shared__ float lsh[L];

    const int b = blockIdx.x;
    const int t = threadIdx.x;

    // reduce split-K partials + ReLU
    {
        float v = 0.f;
        #pragma unroll
        for (int p = 0; p < KS; ++p)
            v += g_h1p[(long)p * (B * H1) + (long)b * H1 + t];
        hsh[t] = fmaxf(v, 0.f);
    }
    __syncthreads();

    // GEMM2: 4-way k split, all 256 threads active
    {
        const int j  = t % H2;
        const int kg = t / H2;
        float acc = 0.f;
        #pragma unroll 8
        for (int k = kg * 64; k < (kg + 1) * 64; ++k)
            acc = fmaf(hsh[k], W2[k * H2 + j], acc);
        p2sh[kg][j] = acc;
    }
    __syncthreads();

    if (t < H2) {
        float acc = b2[t] + p2sh[0][t] + p2sh[1][t] + p2sh[2][t] + p2sh[3][t];
        h2sh[t] = fmaxf(acc, 0.f);
    }
    __syncthreads();

    // GEMM3 (tiny: 4 outputs x 64 k)
    if (t < L) {
        float acc = b3[t];
        #pragma unroll
        for (int k = 0; k < H2; ++k)
            acc = fmaf(h2sh[k], W3[k * L + t], acc);
        lsh[t] = acc;
    }
    __syncthreads();

    // softmax over L=4 (each of 4 threads recomputes — deterministic)
    if (t < L) {
        float mx = lsh[0];
        #pragma unroll
        for (int l = 1; l < L; ++l) mx = fmaxf(mx, lsh[l]);
        float s = 0.f;
        #pragma unroll
        for (int l = 0; l < L; ++l) s += expf(lsh[l] - mx);
        out[b * L + t] = expf(lsh[t] - mx) / s;
    }
}

// ---------------------------------------------------------------------------
extern "C" void kernel_launch(void* const* d_in, const int* in_sizes, int n_in,
                              void* d_out, int out_size)
{
    const float* x1 = (const float*)d_in[0];
    const float* x2 = (const float*)d_in[1];
    const int*   s1 = (const int*)d_in[2];
    const int*   e1 = (const int*)d_in[3];
    const int*   s2 = (const int*)d_in[4];
    const int*   e2 = (const int*)d_in[5];
    const float* W1 = (const float*)d_in[6];
    const float* b1 = (const float*)d_in[7];
    const float* W2 = (const float*)d_in[8];
    const float* b2 = (const float*)d_in[9];
    const float* W3 = (const float*)d_in[10];
    const float* b3 = (const float*)d_in[11];
    float* out = (float*)d_out;

    feat_kernel<<<dim3(B, 2, 3), 256>>>(x1, x2, s1, e1, s2, e2);
    gemm1_kernel<<<dim3(B / BM, H1 / BN, KS), 128>>>(W1, b1);
    tail_kernel<<<B, H1>>>(W2, b2, W3, b3, out);
}

// round 9
// speedup vs baseline: 1.0693x; 1.0693x over previous
#include <cuda_runtime.h>
#include <cuda_bf16.h>
#include <math.h>

// Problem constants
#define B   256
#define S   512
#define D   768
#define D4  (D/4)        // 192 float4 per row
#define K4D 3072         // 4*D
#define H1  256
#define H2  64
#define L   4

// GEMM1 tiling
#define BM  32
#define BN  64
#define BK  32
#define KS  16
#define KC  (K4D/KS)     // 192 k per split
#define FS  68           // padded fsh2 row stride (floats), 16B-aligned

// Scratch (device globals — no allocation allowed)
__device__ float g_f[B * K4D];            // features [256, 3072]  (3 MB)
__device__ float g_h1p[KS * B * H1];      // GEMM1 partials [16, 256, 256] (4 MB)

#define FFMA2(d, a, b) \
    asm("fma.rn.f32x2 %0, %1, %2, %0;" : "+l"(d) : "l"(a), "l"(b))

// ---------------------------------------------------------------------------
// K1: feature extraction. grid (B, 2) — blockIdx.y selects x1/x2.
// 768 threads: col = t%192 (float4 lane), rg = t/192 (4-way row split).
// Span loop: predicated unroll-4 -> 4 independent LDG.128 in flight.
// ---------------------------------------------------------------------------
__global__ void __launch_bounds__(768) feat_kernel(
    const float* __restrict__ x1, const float* __restrict__ x2,
    const int* __restrict__ s1a, const int* __restrict__ e1a,
    const int* __restrict__ s2a, const int* __restrict__ e2a)
{
    __shared__ float4 part[4][D4];        // 12 KB

    const int b   = blockIdx.x;
    const int sel = blockIdx.y;
    const int t   = threadIdx.x;
    const int col = t % D4;
    const int rg  = t / D4;

    const float* x = sel ? x2 : x1;
    int s = sel ? s2a[b] : s1a[b];
    int e = sel ? e2a[b] : e1a[b];
    e = max(e, s + 1);
    int lo = max(s, 0), hi = min(e, S);
    int cnt = max(hi - lo, 1);
    float inv = 1.0f / (float)cnt;

    const float4* x4 = reinterpret_cast<const float4*>(x);
    float4* f4 = reinterpret_cast<float4*>(g_f);
    const long base = (long)b * S * D4;
    const long frow = (long)b * (K4D / 4) + sel * (2 * D4);

    // CLS copy (rowgroup 0)
    if (rg == 0)
        f4[frow + col] = x4[base + col];

    // span partial sums: rows lo+rg, step 4; 4 predicated loads per iter
    float4 acc = make_float4(0.f, 0.f, 0.f, 0.f);
    const float4 zero = make_float4(0.f, 0.f, 0.f, 0.f);
    for (int r = lo + rg; r < hi; r += 16) {
        float4 v0, v1, v2, v3;
        v0 = x4[base + (long)r * D4 + col];                     // r < hi known
        v1 = (r + 4  < hi) ? x4[base + (long)(r + 4)  * D4 + col] : zero;
        v2 = (r + 8  < hi) ? x4[base + (long)(r + 8)  * D4 + col] : zero;
        v3 = (r + 12 < hi) ? x4[base + (long)(r + 12) * D4 + col] : zero;
        acc.x += (v0.x + v1.x) + (v2.x + v3.x);
        acc.y += (v0.y + v1.y) + (v2.y + v3.y);
        acc.z += (v0.z + v1.z) + (v2.z + v3.z);
        acc.w += (v0.w + v1.w) + (v2.w + v3.w);
    }
    part[rg][col] = acc;
    __syncthreads();

    if (t < D4) {
        float4 a0 = part[0][t], a1 = part[1][t], a2 = part[2][t], a3 = part[3][t];
        float4 o;
        o.x = (a0.x + a1.x + a2.x + a3.x) * inv;
        o.y = (a0.y + a1.y + a2.y + a3.y) * inv;
        o.z = (a0.z + a1.z + a2.z + a3.z) * inv;
        o.w = (a0.w + a1.w + a2.w + a3.w) * inv;
        f4[frow + D4 + t] = o;
    }
}

// ---------------------------------------------------------------------------
// K2: GEMM1 split-K16, 32x64 tile, 4x4 micro-tile, packed f32x2 FMA.
// f tile stored DUPLICATED in smem ({v,v} float2) so the broadcast operand of
// fma.rn.f32x2 loads directly as a register pair — no pack MOVs.
// grid (B/BM=8, H1/BN=4, KS=16) = 512 blocks, 128 threads (~3.5 blocks/SM).
// ---------------------------------------------------------------------------
__global__ void __launch_bounds__(128) gemm1_kernel(
    const float* __restrict__ W1, const float* __restrict__ b1)
{
    __shared__ float fsh2[BK][FS];        // duplicated f tile, padded: 8.5 KB
    __shared__ float wsh[BK][BN];         // 8 KB

    const int m0 = blockIdx.x * BM;
    const int n0 = blockIdx.y * BN;
    const int kz = blockIdx.z;
    const int k0 = kz * KC;

    const int tid = threadIdx.x;
    const int tx = tid % 16;              // col group: 4 cols each -> 64
    const int ty = tid / 16;              // row group: 4 rows each -> 32

    const float4* gf4 = reinterpret_cast<const float4*>(g_f);
    const float4* w4  = reinterpret_cast<const float4*>(W1);

    const int kq   = tid % 8;
    const int mrow = tid / 8;
    const int nq  = tid % 16;
    const int kr0 = tid / 16;

    unsigned long long acc2[4][2];
    #pragma unroll
    for (int r = 0; r < 4; ++r) { acc2[r][0] = 0ull; acc2[r][1] = 0ull; }

    for (int kt = 0; kt < KC; kt += BK) {
        // load f tile: BM x BK, duplicated per element
        #pragma unroll
        for (int i = 0; i < 2; ++i) {
            int m = mrow + i * 16;
            float4 v = gf4[(long)(m0 + m) * (K4D / 4) + (k0 + kt) / 4 + kq];
            *reinterpret_cast<float2*>(&fsh2[kq * 4 + 0][2 * m]) = make_float2(v.x, v.x);
            *reinterpret_cast<float2*>(&fsh2[kq * 4 + 1][2 * m]) = make_float2(v.y, v.y);
            *reinterpret_cast<float2*>(&fsh2[kq * 4 + 2][2 * m]) = make_float2(v.z, v.z);
            *reinterpret_cast<float2*>(&fsh2[kq * 4 + 3][2 * m]) = make_float2(v.w, v.w);
        }
        // load w tile: BK x BN
        #pragma unroll
        for (int i = 0; i < 4; ++i) {
            int kr = kr0 + i * 8;
            *reinterpret_cast<float4*>(&wsh[kr][nq * 4]) =
                w4[(long)(k0 + kt + kr) * (H1 / 4) + n0 / 4 + nq];
        }
        __syncthreads();

        #pragma unroll
        for (int k = 0; k < BK; ++k) {
            const ulonglong2* fp =
                reinterpret_cast<const ulonglong2*>(&fsh2[k][2 * (ty * 4)]);
            ulonglong2 fa = fp[0];        // m pairs (ty*4+0), (ty*4+1)
            ulonglong2 fb = fp[1];        // m pairs (ty*4+2), (ty*4+3)
            ulonglong2 wp = *reinterpret_cast<const ulonglong2*>(&wsh[k][tx * 4]);
            FFMA2(acc2[0][0], fa.x, wp.x);  FFMA2(acc2[0][1], fa.x, wp.y);
            FFMA2(acc2[1][0], fa.y, wp.x);  FFMA2(acc2[1][1], fa.y, wp.y);
            FFMA2(acc2[2][0], fb.x, wp.x);  FFMA2(acc2[2][1], fb.x, wp.y);
            FFMA2(acc2[3][0], fb.y, wp.x);  FFMA2(acc2[3][1], fb.y, wp.y);
        }
        __syncthreads();
    }

    // epilogue: unpack, fold bias into split 0, store partials
    float* outp = g_h1p + (long)kz * (B * H1);
    #pragma unroll
    for (int r = 0; r < 4; ++r) {
        int m = m0 + ty * 4 + r;
        #pragma unroll
        for (int p = 0; p < 2; ++p) {
            int n = n0 + tx * 4 + p * 2;
            float lo = __uint_as_float((unsigned)(acc2[r][p] & 0xffffffffull));
            float hi = __uint_as_float((unsigned)(acc2[r][p] >> 32));
            if (kz == 0) { lo += b1[n]; hi += b1[n + 1]; }
            outp[(long)m * H1 + n]     = lo;
            outp[(long)m * H1 + n + 1] = hi;
        }
    }
}

// ---------------------------------------------------------------------------
// K3: per-batch fused tail: reduce split-K partials + ReLU -> GEMM2 + ReLU ->
// GEMM3 -> softmax. One block per batch sample, 256 threads.
// ---------------------------------------------------------------------------
__global__ void __launch_bounds__(H1) tail_kernel(
    const float* __restrict__ W2, const float* __restrict__ b2,
    const float* __restrict__ W3, const float* __restrict__ b3,
    float* __restrict__ out)
{
    __shared__ float hsh[H1];
    __shared__ float p2sh[4][H2];
    __shared__ float h2sh[H2];
    __shared__ float lsh[L];

    const int b = blockIdx.x;
    const int t = threadIdx.x;

    // reduce split-K partials + ReLU
    {
        float v = 0.f;
        #pragma unroll
        for (int p = 0; p < KS; ++p)
            v += g_h1p[(long)p * (B * H1) + (long)b * H1 + t];
        hsh[t] = fmaxf(v, 0.f);
    }
    __syncthreads();

    // GEMM2: 4-way k split, all 256 threads active
    {
        const int j  = t % H2;
        const int kg = t / H2;
        float acc = 0.f;
        #pragma unroll 8
        for (int k = kg * 64; k < (kg + 1) * 64; ++k)
            acc = fmaf(hsh[k], W2[k * H2 + j], acc);
        p2sh[kg][j] = acc;
    }
    __syncthreads();

    if (t < H2) {
        float acc = b2[t] + p2sh[0][t] + p2sh[1][t] + p2sh[2][t] + p2sh[3][t];
        h2sh[t] = fmaxf(acc, 0.f);
    }
    __syncthreads();

    // GEMM3 (tiny: 4 outputs x 64 k)
    if (t < L) {
        float acc = b3[t];
        #pragma unroll
        for (int k = 0; k < H2; ++k)
            acc = fmaf(h2sh[k], W3[k * L + t], acc);
        lsh[t] = acc;
    }
    __syncthreads();

    // softmax over L=4 (each of 4 threads recomputes — deterministic)
    if (t < L) {
        float mx = lsh[0];
        #pragma unroll
        for (int l = 1; l < L; ++l) mx = fmaxf(mx, lsh[l]);
        float s = 0.f;
        #pragma unroll
        for (int l = 0; l < L; ++l) s += expf(lsh[l] - mx);
        out[b * L + t] = expf(lsh[t] - mx) / s;
    }
}

// ---------------------------------------------------------------------------
extern "C" void kernel_launch(void* const* d_in, const int* in_sizes, int n_in,
                              void* d_out, int out_size)
{
    const float* x1 = (const float*)d_in[0];
    const float* x2 = (const float*)d_in[1];
    const int*   s1 = (const int*)d_in[2];
    const int*   e1 = (const int*)d_in[3];
    const int*   s2 = (const int*)d_in[4];
    const int*   e2 = (const int*)d_in[5];
    const float* W1 = (const float*)d_in[6];
    const float* b1 = (const float*)d_in[7];
    const float* W2 = (const float*)d_in[8];
    const float* b2 = (const float*)d_in[9];
    const float* W3 = (const float*)d_in[10];
    const float* b3 = (const float*)d_in[11];
    float* out = (float*)d_out;

    feat_kernel<<<dim3(B, 2), 768>>>(x1, x2, s1, e1, s2, e2);
    gemm1_kernel<<<dim3(B / BM, H1 / BN, KS), 128>>>(W1, b1);
    tail_kernel<<<B, H1>>>(W2, b2, W3, b3, out);
}